// round 12
// baseline (speedup 1.0000x reference)
#include <cuda_runtime.h>
#include <cuda_fp16.h>
#include <mma.h>
#include <cstdint>

// Problem constants: N=50000, E=800000, IN_F=H_F=128, OUT_F=3
#define F 128
#define OUTF 3
#define BN_EPS 1e-5f
#define MAXN 50048
#define MAXE 800000
#define SCAN_TILE 4096
#define MAXTILES ((MAXN + SCAN_TILE - 1) / SCAN_TILE)

using namespace nvcuda;

// -------- device scratch (static; zero-initialized at load) --------
// INVARIANT: every kernel_launch call leaves all accumulator state zeroed,
// so graph replays are deterministic (zero-restore pattern, no init kernel).
__device__ __align__(16) __half g_h[MAXN * F];     // x @ conv_w, fp16
__device__ __align__(16) __half g_agg[MAXN * F];   // relu(agg + conv_b), fp16
__device__ float  g_dinv[MAXN];           // deg accum -> dinv (zeroed by gather)
__device__ __align__(16) int g_cnt[MAXN]; // histogram (zeroed by scan_out)
__device__ __align__(16) int g_off[MAXN + 16]; // CSR offsets (overwritten)
__device__ int    g_part[MAXTILES + 1];   // scan partials (overwritten)
__device__ int    g_rank[MAXE];           // per-edge rank (overwritten)
__device__ __align__(16) int2 g_edge[MAXE]; // CSR packed (overwritten)
__device__ float  g_sumf[F];              // BN sums (zeroed by params)
__device__ float  g_sumqf[F];             // BN sumsq (zeroed by params)
__device__ float  g_w2[F * OUTF];         // folded BN-scale * lin_w (overwritten)
__device__ float  g_b2[OUTF];             // folded bias (overwritten)

// ---------------------------------------------------------------
// 1) degree accumulation + histogram + edge rank, 2 edges/thread.
//    g_dinv/g_cnt start at ZERO (self-loop folded in later as +1).
__global__ void deg_kernel(const int* __restrict__ ei,
                           const float* __restrict__ ew, int E) {
    int t = blockIdx.x * blockDim.x + threadIdx.x;
    int e = t * 2;
    if (e + 1 < E) {
        int2 c = *reinterpret_cast<const int2*>(ei + E + e);
        float2 w = *reinterpret_cast<const float2*>(ew + e);
        atomicAdd(&g_dinv[c.x], w.x);
        int r0 = atomicAdd(&g_cnt[c.x], 1);
        atomicAdd(&g_dinv[c.y], w.y);
        int r1 = atomicAdd(&g_cnt[c.y], 1);
        g_rank[e] = r0;
        g_rank[e + 1] = r1;
    } else if (e < E) {
        int c = ei[E + e];
        atomicAdd(&g_dinv[c], ew[e]);
        g_rank[e] = atomicAdd(&g_cnt[c], 1);
    }
}

// 2) per-tile reduction + fused deg->dinv transform (self-loop weight +1)
__global__ void scan_part_kernel(int n) {
    __shared__ int wsum[32];
    int b = blockIdx.x, tid = threadIdx.x;
    int base = b * SCAN_TILE + tid * 4;

#pragma unroll
    for (int k = 0; k < 4; k++) {
        int i = base + k;
        if (i < n) {
            float d = g_dinv[i] + 1.0f;   // + self-loop weight; d >= 1 > 0
            g_dinv[i] = rsqrtf(d);
        }
    }

    int4 v = make_int4(0, 0, 0, 0);
    if (base + 4 <= n) v = *reinterpret_cast<const int4*>(g_cnt + base);
    else {
        if (base + 0 < n) v.x = g_cnt[base + 0];
        if (base + 1 < n) v.y = g_cnt[base + 1];
        if (base + 2 < n) v.z = g_cnt[base + 2];
        if (base + 3 < n) v.w = g_cnt[base + 3];
    }
    int s = v.x + v.y + v.z + v.w;
    int lane = tid & 31, wid = tid >> 5;
#pragma unroll
    for (int off = 16; off > 0; off >>= 1) s += __shfl_down_sync(0xffffffffu, s, off);
    if (lane == 0) wsum[wid] = s;
    __syncthreads();
    if (wid == 0) {
        int t2 = wsum[lane];
#pragma unroll
        for (int off = 16; off > 0; off >>= 1) t2 += __shfl_down_sync(0xffffffffu, t2, off);
        if (lane == 0) g_part[b] = t2;
    }
}

// 3) per-tile exclusive scan-out with cross-tile prefix; zeroes g_cnt after read
__global__ void scan_out_kernel(int n, int ntiles) {
    __shared__ int wsum[32];
    int b = blockIdx.x, tid = threadIdx.x;
    int lane = tid & 31, wid = tid >> 5;

    int prefix = 0;
    for (int i = 0; i < b; i++) prefix += g_part[i];

    int base = b * SCAN_TILE + tid * 4;
    int4 v = make_int4(0, 0, 0, 0);
    bool full = (base + 4 <= n);
    if (full) v = *reinterpret_cast<const int4*>(g_cnt + base);
    else {
        if (base + 0 < n) v.x = g_cnt[base + 0];
        if (base + 1 < n) v.y = g_cnt[base + 1];
        if (base + 2 < n) v.z = g_cnt[base + 2];
        if (base + 3 < n) v.w = g_cnt[base + 3];
    }
    // zero-restore g_cnt for the next replay (last reader of g_cnt)
    if (full) {
        *reinterpret_cast<int4*>(g_cnt + base) = make_int4(0, 0, 0, 0);
    } else {
        if (base + 0 < n) g_cnt[base + 0] = 0;
        if (base + 1 < n) g_cnt[base + 1] = 0;
        if (base + 2 < n) g_cnt[base + 2] = 0;
        if (base + 3 < n) g_cnt[base + 3] = 0;
    }

    int s0 = v.x, s1 = s0 + v.y, s2 = s1 + v.z, s3 = s2 + v.w;

    int p = s3;
#pragma unroll
    for (int off = 1; off < 32; off <<= 1) {
        int tmp = __shfl_up_sync(0xffffffffu, p, off);
        if (lane >= off) p += tmp;
    }
    if (lane == 31) wsum[wid] = p;
    __syncthreads();
    if (wid == 0) {
        int w = wsum[lane];
#pragma unroll
        for (int off = 1; off < 32; off <<= 1) {
            int tmp = __shfl_up_sync(0xffffffffu, w, off);
            if (lane >= off) w += tmp;
        }
        wsum[lane] = w;
    }
    __syncthreads();

    int excl = prefix + (wid > 0 ? wsum[wid - 1] : 0) + (p - s3);
    if (full) {
        *reinterpret_cast<int4*>(g_off + base) =
            make_int4(excl, excl + s0, excl + s1, excl + s2);
    } else {
        if (base + 0 < n) g_off[base + 0] = excl;
        if (base + 1 < n) g_off[base + 1] = excl + s0;
        if (base + 2 < n) g_off[base + 2] = excl + s1;
        if (base + 3 < n) g_off[base + 3] = excl + s2;
    }
    if (b == ntiles - 1 && tid == 0) g_off[n] = prefix + g_part[b];
}

// 4) fill CSR slots: NO atomics — slot = g_off[c] + precomputed rank
__global__ void fill_kernel(const int* __restrict__ ei,
                            const float* __restrict__ ew, int E) {
    int e = blockIdx.x * blockDim.x + threadIdx.x;
    if (e >= E) return;
    int r = ei[e];
    int c = ei[E + e];
    int j = g_off[c] + g_rank[e];
    float nrm = g_dinv[r] * ew[e] * g_dinv[c];
    g_edge[j] = make_int2(r, __float_as_int(nrm));
}

// ---------------------------------------------------------------
// 5) GEMM via HMMA: h[N,128] = x[N,128] @ w[128,128]
#define XLD 136   // half leading dim (padded)
__global__ __launch_bounds__(256)
void gemm_kernel(const float* __restrict__ x, const float* __restrict__ w, int n) {
    extern __shared__ __half sh[];
    __half* xs = sh;                 // [128][XLD]
    __half* ws = sh + 128 * XLD;     // [128][XLD]

    int tid = threadIdx.x;
    int lane = tid & 31;
    int warp = tid >> 5;             // 0..7
    int m0 = blockIdx.x * 128;

    for (int s = tid; s < 4096; s += 256) {
        int r = s >> 5, c4 = s & 31;
        float4 v = reinterpret_cast<const float4*>(w + (size_t)r * F)[c4];
        __half2 h0 = __floats2half2_rn(v.x, v.y);
        __half2 h1 = __floats2half2_rn(v.z, v.w);
        __half2* dst = reinterpret_cast<__half2*>(ws + r * XLD + c4 * 4);
        dst[0] = h0; dst[1] = h1;
    }
    for (int s = tid; s < 4096; s += 256) {
        int r = s >> 5, c4 = s & 31;
        float4 v = make_float4(0.f, 0.f, 0.f, 0.f);
        if (m0 + r < n)
            v = reinterpret_cast<const float4*>(x + (size_t)(m0 + r) * F)[c4];
        __half2 h0 = __floats2half2_rn(v.x, v.y);
        __half2 h1 = __floats2half2_rn(v.z, v.w);
        __half2* dst = reinterpret_cast<__half2*>(xs + r * XLD + c4 * 4);
        dst[0] = h0; dst[1] = h1;
    }
    __syncthreads();

    wmma::fragment<wmma::accumulator, 16, 16, 16, float> acc[8];
#pragma unroll
    for (int j = 0; j < 8; j++) wmma::fill_fragment(acc[j], 0.0f);

    int row0 = warp * 16;
#pragma unroll
    for (int k = 0; k < 128; k += 16) {
        wmma::fragment<wmma::matrix_a, 16, 16, 16, __half, wmma::row_major> a;
        wmma::load_matrix_sync(a, xs + row0 * XLD + k, XLD);
#pragma unroll
        for (int j = 0; j < 8; j++) {
            wmma::fragment<wmma::matrix_b, 16, 16, 16, __half, wmma::row_major> b;
            wmma::load_matrix_sync(b, ws + k * XLD + j * 16, XLD);
            wmma::mma_sync(acc[j], a, b, acc[j]);
        }
    }
    __syncthreads();

    float* cs = reinterpret_cast<float*>(sh);
    float* my = cs + warp * 16 * 128;
#pragma unroll
    for (int j = 0; j < 8; j++)
        wmma::store_matrix_sync(my + j * 16, acc[j], 128, wmma::mem_row_major);
    __syncwarp();

    for (int s = lane; s < 512; s += 32) {
        int r = s >> 5, c4 = s & 31;
        int node = m0 + row0 + r;
        if (node < n) {
            float4 v = reinterpret_cast<const float4*>(my + r * 128)[c4];
            __half2 h0 = __floats2half2_rn(v.x, v.y);
            __half2 h1 = __floats2half2_rn(v.z, v.w);
            uint2 u;
            u.x = *reinterpret_cast<unsigned*>(&h0);
            u.y = *reinterpret_cast<unsigned*>(&h1);
            reinterpret_cast<uint2*>(g_h + (size_t)node * F)[c4] = u;
        }
    }
}

// ---------------------------------------------------------------
// helper: load 4 features (fp16) of a row as floats
__device__ __forceinline__ void load_row4(int row, int lane,
                                          float& a, float& b, float& c, float& d) {
    uint2 u = reinterpret_cast<const uint2*>(g_h + (size_t)row * F)[lane];
    __half2 h0 = *reinterpret_cast<__half2*>(&u.x);
    __half2 h1 = *reinterpret_cast<__half2*>(&u.y);
    float2 f0 = __half22float2(h0);
    float2 f1 = __half22float2(h1);
    a = f0.x; b = f0.y; c = f1.x; d = f1.y;
}

// 6) fused gather + relu/bias + BN stats (persistent grid-stride).
//    Zeroes g_dinv after its final read (zero-restore for next replay).
__global__ __launch_bounds__(256)
void gather_kernel(const float* __restrict__ conv_b, int n, int nwarps_total) {
    __shared__ float sms[8][132];
    __shared__ float smq[8][132];

    int lane = threadIdx.x & 31;
    int w = threadIdx.x >> 5;
    int gwarp = blockIdx.x * 8 + w;

    int f = lane * 4;
    float b0 = __ldg(conv_b + f + 0), b1 = __ldg(conv_b + f + 1);
    float b2 = __ldg(conv_b + f + 2), b3 = __ldg(conv_b + f + 3);

    float s0 = 0.f, s1 = 0.f, s2 = 0.f, s3 = 0.f;   // BN sums
    float q0 = 0.f, q1 = 0.f, q2 = 0.f, q3 = 0.f;   // BN sumsq

    for (int node = gwarp; node < n; node += nwarps_total) {
        float d = g_dinv[node];
        if (lane == 0) g_dinv[node] = 0.0f;   // zero-restore (last reader)
        float sc = d * d;
        float a0, a1, a2, a3;
        load_row4(node, lane, a0, a1, a2, a3);
        a0 *= sc; a1 *= sc; a2 *= sc; a3 *= sc;

        int j = g_off[node];
        int jend = g_off[node + 1];
        for (; j + 3 < jend; j += 4) {
            int2 e0 = g_edge[j],   e1 = g_edge[j+1];
            int2 e2 = g_edge[j+2], e3 = g_edge[j+3];
            float w0 = __int_as_float(e0.y), w1 = __int_as_float(e1.y);
            float w2 = __int_as_float(e2.y), w3 = __int_as_float(e3.y);
            float x0,x1,x2,x3, y0,y1,y2,y3, z0,z1,z2,z3, t0,t1,t2,t3;
            load_row4(e0.x, lane, x0, x1, x2, x3);
            load_row4(e1.x, lane, y0, y1, y2, y3);
            load_row4(e2.x, lane, z0, z1, z2, z3);
            load_row4(e3.x, lane, t0, t1, t2, t3);
            a0 += w0*x0 + w1*y0 + w2*z0 + w3*t0;
            a1 += w0*x1 + w1*y1 + w2*z1 + w3*t1;
            a2 += w0*x2 + w1*y2 + w2*z2 + w3*t2;
            a3 += w0*x3 + w1*y3 + w2*z3 + w3*t3;
        }
        for (; j < jend; j++) {
            int2 e = g_edge[j];
            float ww = __int_as_float(e.y);
            float x0, x1, x2, x3;
            load_row4(e.x, lane, x0, x1, x2, x3);
            a0 += ww*x0; a1 += ww*x1; a2 += ww*x2; a3 += ww*x3;
        }

        float r0 = fmaxf(a0 + b0, 0.f);
        float r1 = fmaxf(a1 + b1, 0.f);
        float r2 = fmaxf(a2 + b2, 0.f);
        float r3 = fmaxf(a3 + b3, 0.f);

        __half2 h0 = __floats2half2_rn(r0, r1);
        __half2 h1 = __floats2half2_rn(r2, r3);
        uint2 u;
        u.x = *reinterpret_cast<unsigned*>(&h0);
        u.y = *reinterpret_cast<unsigned*>(&h1);
        reinterpret_cast<uint2*>(g_agg + (size_t)node * F)[lane] = u;

        s0 += r0; s1 += r1; s2 += r2; s3 += r3;
        q0 += r0*r0; q1 += r1*r1; q2 += r2*r2; q3 += r3*r3;
    }

    sms[w][f + 0] = s0; sms[w][f + 1] = s1; sms[w][f + 2] = s2; sms[w][f + 3] = s3;
    smq[w][f + 0] = q0; smq[w][f + 1] = q1; smq[w][f + 2] = q2; smq[w][f + 3] = q3;
    __syncthreads();
    int t = threadIdx.x;
    if (t < F) {
        float s = 0.f, q = 0.f;
#pragma unroll
        for (int g = 0; g < 8; g++) { s += sms[g][t]; q += smq[g][t]; }
        atomicAdd(&g_sumf[t], s);
        atomicAdd(&g_sumqf[t], q);
    }
}

// 7) fold BN affine into final projection; zeroes BN accumulators after read
__global__ void params_kernel(const float* __restrict__ gamma,
                              const float* __restrict__ beta,
                              const float* __restrict__ lin_w,
                              const float* __restrict__ lin_b, int n) {
    __shared__ float partial[F][OUTF];
    int f = threadIdx.x;   // 128 threads
    float inv_n = 1.0f / (float)n;
    float sum = g_sumf[f], sumq = g_sumqf[f];
    g_sumf[f] = 0.0f;      // zero-restore (last reader)
    g_sumqf[f] = 0.0f;
    float mean = sum * inv_n;
    float var  = sumq * inv_n - mean * mean;
    float sc = gamma[f] * rsqrtf(var + BN_EPS);
    float sh = beta[f] - mean * sc;
#pragma unroll
    for (int o = 0; o < OUTF; o++) {
        float lw = lin_w[f * OUTF + o];
        g_w2[f * OUTF + o] = sc * lw;
        partial[f][o] = sh * lw;
    }
    __syncthreads();
    if (f < OUTF) {
        float t = lin_b[f];
        for (int i = 0; i < F; i++) t += partial[i][f];
        g_b2[f] = t;
    }
}

// 8) final: out[n,3] = r @ w2 + b2  (r fp16 in g_agg)
__global__ void final_kernel(float* __restrict__ out, int n) {
    __shared__ float w2s[F * OUTF];
    __shared__ float b2s[OUTF];
    for (int i = threadIdx.x; i < F * OUTF; i += blockDim.x) w2s[i] = g_w2[i];
    if (threadIdx.x < OUTF) b2s[threadIdx.x] = g_b2[threadIdx.x];
    __syncthreads();

    int gtid = blockIdx.x * blockDim.x + threadIdx.x;
    int node = gtid >> 5;
    int lane = gtid & 31;
    if (node >= n) return;

    uint2 u = reinterpret_cast<const uint2*>(g_agg + (size_t)node * F)[lane];
    __half2 h0 = *reinterpret_cast<__half2*>(&u.x);
    __half2 h1 = *reinterpret_cast<__half2*>(&u.y);
    float2 f0 = __half22float2(h0);
    float2 f1 = __half22float2(h1);
    float r[4] = {f0.x, f0.y, f1.x, f1.y};

    float a0 = 0.f, a1 = 0.f, a2 = 0.f;
#pragma unroll
    for (int i = 0; i < 4; i++) {
        int f = lane * 4 + i;
        a0 += r[i] * w2s[f * OUTF + 0];
        a1 += r[i] * w2s[f * OUTF + 1];
        a2 += r[i] * w2s[f * OUTF + 2];
    }
#pragma unroll
    for (int off = 16; off > 0; off >>= 1) {
        a0 += __shfl_down_sync(0xffffffffu, a0, off);
        a1 += __shfl_down_sync(0xffffffffu, a1, off);
        a2 += __shfl_down_sync(0xffffffffu, a2, off);
    }
    if (lane == 0) {
        out[node * OUTF + 0] = a0 + b2s[0];
        out[node * OUTF + 1] = a1 + b2s[1];
        out[node * OUTF + 2] = a2 + b2s[2];
    }
}

// ---------------------------------------------------------------
extern "C" void kernel_launch(void* const* d_in, const int* in_sizes, int n_in,
                              void* d_out, int out_size) {
    const float* x      = (const float*)d_in[0];
    const int*   ei     = (const int*)d_in[1];     // int32 (JAX x64 disabled)
    const float* ew     = (const float*)d_in[2];
    const float* conv_w = (const float*)d_in[3];
    const float* conv_b = (const float*)d_in[4];
    const float* gamma  = (const float*)d_in[5];
    const float* beta   = (const float*)d_in[6];
    const float* lin_w  = (const float*)d_in[7];
    const float* lin_b  = (const float*)d_in[8];
    float* out = (float*)d_out;

    int n = in_sizes[0] / F;        // 50000
    int E = in_sizes[2];            // 800000
    int ntiles = (n + SCAN_TILE - 1) / SCAN_TILE;

    const int GEMM_SMEM = 2 * 128 * XLD * (int)sizeof(__half);   // 69632 B
    static bool attr_set = false;
    if (!attr_set) {
        cudaFuncSetAttribute(gemm_kernel,
                             cudaFuncAttributeMaxDynamicSharedMemorySize, GEMM_SMEM);
        attr_set = true;
    }

    const int GATHER_BLOCKS = 1184;
    int nwarps_total = GATHER_BLOCKS * 8;

    deg_kernel<<<((E + 1) / 2 + 255) / 256, 256>>>(ei, ew, E);
    scan_part_kernel<<<ntiles, 1024>>>(n);
    scan_out_kernel<<<ntiles, 1024>>>(n, ntiles);
    fill_kernel<<<(E + 255) / 256, 256>>>(ei, ew, E);
    gemm_kernel<<<(n + 127) / 128, 256, GEMM_SMEM>>>(x, conv_w, n);
    gather_kernel<<<GATHER_BLOCKS, 256>>>(conv_b, n, nwarps_total);
    params_kernel<<<1, 128>>>(gamma, beta, lin_w, lin_b, n);
    final_kernel<<<(n * 32 + 255) / 256, 256>>>(out, n);
}

// round 13
// speedup vs baseline: 1.6387x; 1.6387x over previous
#include <cuda_runtime.h>
#include <cuda_fp16.h>
#include <mma.h>
#include <cstdint>

// Problem constants: N=50000, E=800000, IN_F=H_F=128, OUT_F=3
#define F 128
#define OUTF 3
#define BN_EPS 1e-5f
#define MAXN 50048
#define MAXE 800000
#define SCAN_TILE 4096
#define MAXTILES ((MAXN + SCAN_TILE - 1) / SCAN_TILE)

using namespace nvcuda;

// -------- device scratch (static; no dynamic allocations) --------
__device__ __align__(16) __half g_h[MAXN * F];   // x @ conv_w, fp16 storage
__device__ float  g_agg[MAXN * F];        // relu(agg + conv_b), fp32
__device__ float  g_dinv[MAXN];           // deg -> dinv (in place)
__device__ __align__(16) int g_cnt[MAXN]; // in-degree histogram
__device__ int    g_cur[MAXN];            // placement cursors
__device__ __align__(16) int g_off[MAXN + 16]; // CSR offsets (padded)
__device__ int    g_part[MAXTILES + 1];   // scan partials
__device__ __align__(16) int2 g_edge[MAXE]; // CSR: packed (src, norm-as-int)
__device__ float  g_sumf[F];              // BN sums
__device__ float  g_sumqf[F];             // BN sum of squares
__device__ float  g_w2[F * OUTF];         // folded BN-scale * lin_w
__device__ float  g_b2[OUTF];             // folded bias

// ---------------------------------------------------------------
// 1) init
__global__ void init_kernel(int n) {
    int i = blockIdx.x * blockDim.x + threadIdx.x;
    if (i < n) { g_dinv[i] = 1.0f; g_cnt[i] = 0; g_cur[i] = 0; }
    if (i < F) { g_sumf[i] = 0.0f; g_sumqf[i] = 0.0f; }
}

// 2) degree accumulation + in-degree histogram (edge_index is int32)
__global__ void deg_kernel(const int* __restrict__ ei,
                           const float* __restrict__ ew, int E) {
    int t = blockIdx.x * blockDim.x + threadIdx.x;
    int e = t * 2;
    if (e + 1 < E) {
        int2 c = *reinterpret_cast<const int2*>(ei + E + e);
        float2 w = *reinterpret_cast<const float2*>(ew + e);
        atomicAdd(&g_dinv[c.x], w.x);
        atomicAdd(&g_cnt[c.x], 1);
        atomicAdd(&g_dinv[c.y], w.y);
        atomicAdd(&g_cnt[c.y], 1);
    } else if (e < E) {
        int c = ei[E + e];
        atomicAdd(&g_dinv[c], ew[e]);
        atomicAdd(&g_cnt[c], 1);
    }
}

// 3) per-tile reduction (+ fused deg->dinv transform for the same range)
__global__ void scan_part_kernel(int n) {
    __shared__ int wsum[32];
    int b = blockIdx.x, tid = threadIdx.x;
    int base = b * SCAN_TILE + tid * 4;

#pragma unroll
    for (int k = 0; k < 4; k++) {
        int i = base + k;
        if (i < n) {
            float d = g_dinv[i];
            g_dinv[i] = (d > 0.0f) ? rsqrtf(d) : 0.0f;
        }
    }

    int4 v = make_int4(0, 0, 0, 0);
    if (base + 4 <= n) v = *reinterpret_cast<const int4*>(g_cnt + base);
    else {
        if (base + 0 < n) v.x = g_cnt[base + 0];
        if (base + 1 < n) v.y = g_cnt[base + 1];
        if (base + 2 < n) v.z = g_cnt[base + 2];
        if (base + 3 < n) v.w = g_cnt[base + 3];
    }
    int s = v.x + v.y + v.z + v.w;
    int lane = tid & 31, wid = tid >> 5;
#pragma unroll
    for (int off = 16; off > 0; off >>= 1) s += __shfl_down_sync(0xffffffffu, s, off);
    if (lane == 0) wsum[wid] = s;
    __syncthreads();
    if (wid == 0) {
        int t2 = wsum[lane];
#pragma unroll
        for (int off = 16; off > 0; off >>= 1) t2 += __shfl_down_sync(0xffffffffu, t2, off);
        if (lane == 0) g_part[b] = t2;
    }
}

// 4) per-tile exclusive scan-out with cross-tile prefix
__global__ void scan_out_kernel(int n, int ntiles) {
    __shared__ int wsum[32];
    int b = blockIdx.x, tid = threadIdx.x;
    int lane = tid & 31, wid = tid >> 5;

    int prefix = 0;
    for (int i = 0; i < b; i++) prefix += g_part[i];

    int base = b * SCAN_TILE + tid * 4;
    int4 v = make_int4(0, 0, 0, 0);
    bool full = (base + 4 <= n);
    if (full) v = *reinterpret_cast<const int4*>(g_cnt + base);
    else {
        if (base + 0 < n) v.x = g_cnt[base + 0];
        if (base + 1 < n) v.y = g_cnt[base + 1];
        if (base + 2 < n) v.z = g_cnt[base + 2];
        if (base + 3 < n) v.w = g_cnt[base + 3];
    }
    int s0 = v.x, s1 = s0 + v.y, s2 = s1 + v.z, s3 = s2 + v.w;

    int p = s3;
#pragma unroll
    for (int off = 1; off < 32; off <<= 1) {
        int tmp = __shfl_up_sync(0xffffffffu, p, off);
        if (lane >= off) p += tmp;
    }
    if (lane == 31) wsum[wid] = p;
    __syncthreads();
    if (wid == 0) {
        int w = wsum[lane];
#pragma unroll
        for (int off = 1; off < 32; off <<= 1) {
            int tmp = __shfl_up_sync(0xffffffffu, w, off);
            if (lane >= off) w += tmp;
        }
        wsum[lane] = w;
    }
    __syncthreads();

    int excl = prefix + (wid > 0 ? wsum[wid - 1] : 0) + (p - s3);
    if (full) {
        *reinterpret_cast<int4*>(g_off + base) =
            make_int4(excl, excl + s0, excl + s1, excl + s2);
    } else {
        if (base + 0 < n) g_off[base + 0] = excl;
        if (base + 1 < n) g_off[base + 1] = excl + s0;
        if (base + 2 < n) g_off[base + 2] = excl + s1;
        if (base + 3 < n) g_off[base + 3] = excl + s2;
    }
    if (b == ntiles - 1 && tid == 0) g_off[n] = prefix + g_part[b];
}

// 5) fill CSR slots: one packed int2 store per edge
__global__ void fill_kernel(const int* __restrict__ ei,
                            const float* __restrict__ ew, int E) {
    int e = blockIdx.x * blockDim.x + threadIdx.x;
    if (e >= E) return;
    int r = ei[e];
    int c = ei[E + e];
    int j = g_off[c] + atomicAdd(&g_cur[c], 1);
    float nrm = g_dinv[r] * ew[e] * g_dinv[c];
    g_edge[j] = make_int2(r, __float_as_int(nrm));
}

// ---------------------------------------------------------------
// 6) GEMM via HMMA: h[N,128] = x[N,128] @ w[128,128]
#define XLD 136   // half leading dim (padded)
__global__ __launch_bounds__(256)
void gemm_kernel(const float* __restrict__ x, const float* __restrict__ w, int n) {
    extern __shared__ __half sh[];
    __half* xs = sh;                 // [128][XLD]
    __half* ws = sh + 128 * XLD;     // [128][XLD]

    int tid = threadIdx.x;
    int lane = tid & 31;
    int warp = tid >> 5;             // 0..7
    int m0 = blockIdx.x * 128;

    for (int s = tid; s < 4096; s += 256) {
        int r = s >> 5, c4 = s & 31;
        float4 v = reinterpret_cast<const float4*>(w + (size_t)r * F)[c4];
        __half2 h0 = __floats2half2_rn(v.x, v.y);
        __half2 h1 = __floats2half2_rn(v.z, v.w);
        __half2* dst = reinterpret_cast<__half2*>(ws + r * XLD + c4 * 4);
        dst[0] = h0; dst[1] = h1;
    }
    for (int s = tid; s < 4096; s += 256) {
        int r = s >> 5, c4 = s & 31;
        float4 v = make_float4(0.f, 0.f, 0.f, 0.f);
        if (m0 + r < n)
            v = reinterpret_cast<const float4*>(x + (size_t)(m0 + r) * F)[c4];
        __half2 h0 = __floats2half2_rn(v.x, v.y);
        __half2 h1 = __floats2half2_rn(v.z, v.w);
        __half2* dst = reinterpret_cast<__half2*>(xs + r * XLD + c4 * 4);
        dst[0] = h0; dst[1] = h1;
    }
    __syncthreads();

    wmma::fragment<wmma::accumulator, 16, 16, 16, float> acc[8];
#pragma unroll
    for (int j = 0; j < 8; j++) wmma::fill_fragment(acc[j], 0.0f);

    int row0 = warp * 16;
#pragma unroll
    for (int k = 0; k < 128; k += 16) {
        wmma::fragment<wmma::matrix_a, 16, 16, 16, __half, wmma::row_major> a;
        wmma::load_matrix_sync(a, xs + row0 * XLD + k, XLD);
#pragma unroll
        for (int j = 0; j < 8; j++) {
            wmma::fragment<wmma::matrix_b, 16, 16, 16, __half, wmma::row_major> b;
            wmma::load_matrix_sync(b, ws + k * XLD + j * 16, XLD);
            wmma::mma_sync(acc[j], a, b, acc[j]);
        }
    }
    __syncthreads();

    float* cs = reinterpret_cast<float*>(sh);
    float* my = cs + warp * 16 * 128;
#pragma unroll
    for (int j = 0; j < 8; j++)
        wmma::store_matrix_sync(my + j * 16, acc[j], 128, wmma::mem_row_major);
    __syncwarp();

    for (int s = lane; s < 512; s += 32) {
        int r = s >> 5, c4 = s & 31;
        int node = m0 + row0 + r;
        if (node < n) {
            float4 v = reinterpret_cast<const float4*>(my + r * 128)[c4];
            __half2 h0 = __floats2half2_rn(v.x, v.y);
            __half2 h1 = __floats2half2_rn(v.z, v.w);
            uint2 u;
            u.x = *reinterpret_cast<unsigned*>(&h0);
            u.y = *reinterpret_cast<unsigned*>(&h1);
            reinterpret_cast<uint2*>(g_h + (size_t)node * F)[c4] = u;
        }
    }
}

// ---------------------------------------------------------------
// helper: load 4 features (fp16) of a row as floats
__device__ __forceinline__ void load_row4(int row, int lane,
                                          float& a, float& b, float& c, float& d) {
    uint2 u = reinterpret_cast<const uint2*>(g_h + (size_t)row * F)[lane];
    __half2 h0 = *reinterpret_cast<__half2*>(&u.x);
    __half2 h1 = *reinterpret_cast<__half2*>(&u.y);
    float2 f0 = __half22float2(h0);
    float2 f1 = __half22float2(h1);
    a = f0.x; b = f0.y; c = f1.x; d = f1.y;
}

// 7) fused gather + relu/bias + BN stats (persistent grid-stride)
__global__ __launch_bounds__(256)
void gather_kernel(const float* __restrict__ conv_b, int n, int nwarps_total) {
    __shared__ float sms[8][132];
    __shared__ float smq[8][132];

    int lane = threadIdx.x & 31;
    int w = threadIdx.x >> 5;
    int gwarp = blockIdx.x * 8 + w;

    int f = lane * 4;
    float b0 = __ldg(conv_b + f + 0), b1 = __ldg(conv_b + f + 1);
    float b2 = __ldg(conv_b + f + 2), b3 = __ldg(conv_b + f + 3);

    float s0 = 0.f, s1 = 0.f, s2 = 0.f, s3 = 0.f;   // BN sums
    float q0 = 0.f, q1 = 0.f, q2 = 0.f, q3 = 0.f;   // BN sumsq

    for (int node = gwarp; node < n; node += nwarps_total) {
        float d = g_dinv[node];
        float sc = d * d;
        float a0, a1, a2, a3;
        load_row4(node, lane, a0, a1, a2, a3);
        a0 *= sc; a1 *= sc; a2 *= sc; a3 *= sc;

        int j = g_off[node];
        int jend = g_off[node + 1];
        for (; j + 3 < jend; j += 4) {
            int2 e0 = g_edge[j],   e1 = g_edge[j+1];
            int2 e2 = g_edge[j+2], e3 = g_edge[j+3];
            float w0 = __int_as_float(e0.y), w1 = __int_as_float(e1.y);
            float w2 = __int_as_float(e2.y), w3 = __int_as_float(e3.y);
            float x0,x1,x2,x3, y0,y1,y2,y3, z0,z1,z2,z3, t0,t1,t2,t3;
            load_row4(e0.x, lane, x0, x1, x2, x3);
            load_row4(e1.x, lane, y0, y1, y2, y3);
            load_row4(e2.x, lane, z0, z1, z2, z3);
            load_row4(e3.x, lane, t0, t1, t2, t3);
            a0 += w0*x0 + w1*y0 + w2*z0 + w3*t0;
            a1 += w0*x1 + w1*y1 + w2*z1 + w3*t1;
            a2 += w0*x2 + w1*y2 + w2*z2 + w3*t2;
            a3 += w0*x3 + w1*y3 + w2*z3 + w3*t3;
        }
        for (; j < jend; j++) {
            int2 e = g_edge[j];
            float ww = __int_as_float(e.y);
            float x0, x1, x2, x3;
            load_row4(e.x, lane, x0, x1, x2, x3);
            a0 += ww*x0; a1 += ww*x1; a2 += ww*x2; a3 += ww*x3;
        }

        float r0 = fmaxf(a0 + b0, 0.f);
        float r1 = fmaxf(a1 + b1, 0.f);
        float r2 = fmaxf(a2 + b2, 0.f);
        float r3 = fmaxf(a3 + b3, 0.f);
        reinterpret_cast<float4*>(g_agg + (size_t)node * F)[lane] =
            make_float4(r0, r1, r2, r3);

        s0 += r0; s1 += r1; s2 += r2; s3 += r3;
        q0 += r0*r0; q1 += r1*r1; q2 += r2*r2; q3 += r3*r3;
    }

    sms[w][f + 0] = s0; sms[w][f + 1] = s1; sms[w][f + 2] = s2; sms[w][f + 3] = s3;
    smq[w][f + 0] = q0; smq[w][f + 1] = q1; smq[w][f + 2] = q2; smq[w][f + 3] = q3;
    __syncthreads();
    int t = threadIdx.x;
    if (t < F) {
        float s = 0.f, q = 0.f;
#pragma unroll
        for (int g = 0; g < 8; g++) { s += sms[g][t]; q += smq[g][t]; }
        atomicAdd(&g_sumf[t], s);
        atomicAdd(&g_sumqf[t], q);
    }
}

// 8) fold BN affine into final projection
__global__ void params_kernel(const float* __restrict__ gamma,
                              const float* __restrict__ beta,
                              const float* __restrict__ lin_w,
                              const float* __restrict__ lin_b, int n) {
    __shared__ float partial[F][OUTF];
    int f = threadIdx.x;   // 128 threads
    float inv_n = 1.0f / (float)n;
    float mean = g_sumf[f] * inv_n;
    float var  = g_sumqf[f] * inv_n - mean * mean;
    float sc = gamma[f] * rsqrtf(var + BN_EPS);
    float sh = beta[f] - mean * sc;
#pragma unroll
    for (int o = 0; o < OUTF; o++) {
        float lw = lin_w[f * OUTF + o];
        g_w2[f * OUTF + o] = sc * lw;
        partial[f][o] = sh * lw;
    }
    __syncthreads();
    if (f < OUTF) {
        float t = lin_b[f];
        for (int i = 0; i < F; i++) t += partial[i][f];
        g_b2[f] = t;
    }
}

// 9) final: out[n,3] = r @ w2 + b2
__global__ void final_kernel(float* __restrict__ out, int n) {
    __shared__ float w2s[F * OUTF];
    __shared__ float b2s[OUTF];
    for (int i = threadIdx.x; i < F * OUTF; i += blockDim.x) w2s[i] = g_w2[i];
    if (threadIdx.x < OUTF) b2s[threadIdx.x] = g_b2[threadIdx.x];
    __syncthreads();

    int gtid = blockIdx.x * blockDim.x + threadIdx.x;
    int node = gtid >> 5;
    int lane = gtid & 31;
    if (node >= n) return;

    float4 v = reinterpret_cast<const float4*>(g_agg + (size_t)node * F)[lane];
    float r[4] = {v.x, v.y, v.z, v.w};

    float a0 = 0.f, a1 = 0.f, a2 = 0.f;
#pragma unroll
    for (int i = 0; i < 4; i++) {
        int f = lane * 4 + i;
        a0 += r[i] * w2s[f * OUTF + 0];
        a1 += r[i] * w2s[f * OUTF + 1];
        a2 += r[i] * w2s[f * OUTF + 2];
    }
#pragma unroll
    for (int off = 16; off > 0; off >>= 1) {
        a0 += __shfl_down_sync(0xffffffffu, a0, off);
        a1 += __shfl_down_sync(0xffffffffu, a1, off);
        a2 += __shfl_down_sync(0xffffffffu, a2, off);
    }
    if (lane == 0) {
        out[node * OUTF + 0] = a0 + b2s[0];
        out[node * OUTF + 1] = a1 + b2s[1];
        out[node * OUTF + 2] = a2 + b2s[2];
    }
}

// ---------------------------------------------------------------
extern "C" void kernel_launch(void* const* d_in, const int* in_sizes, int n_in,
                              void* d_out, int out_size) {
    const float* x      = (const float*)d_in[0];
    const int*   ei     = (const int*)d_in[1];     // int32 (JAX x64 disabled)
    const float* ew     = (const float*)d_in[2];
    const float* conv_w = (const float*)d_in[3];
    const float* conv_b = (const float*)d_in[4];
    const float* gamma  = (const float*)d_in[5];
    const float* beta   = (const float*)d_in[6];
    const float* lin_w  = (const float*)d_in[7];
    const float* lin_b  = (const float*)d_in[8];
    float* out = (float*)d_out;

    int n = in_sizes[0] / F;        // 50000
    int E = in_sizes[2];            // 800000
    int ntiles = (n + SCAN_TILE - 1) / SCAN_TILE;

    const int GEMM_SMEM = 2 * 128 * XLD * (int)sizeof(__half);   // 69632 B
    static bool attr_set = false;
    if (!attr_set) {
        cudaFuncSetAttribute(gemm_kernel,
                             cudaFuncAttributeMaxDynamicSharedMemorySize, GEMM_SMEM);
        attr_set = true;
    }

    const int GATHER_BLOCKS = 1184;
    int nwarps_total = GATHER_BLOCKS * 8;

    init_kernel<<<(n + 255) / 256, 256>>>(n);
    deg_kernel<<<((E + 1) / 2 + 255) / 256, 256>>>(ei, ew, E);
    scan_part_kernel<<<ntiles, 1024>>>(n);
    scan_out_kernel<<<ntiles, 1024>>>(n, ntiles);
    fill_kernel<<<(E + 255) / 256, 256>>>(ei, ew, E);
    gemm_kernel<<<(n + 127) / 128, 256, GEMM_SMEM>>>(x, conv_w, n);
    gather_kernel<<<GATHER_BLOCKS, 256>>>(conv_b, n, nwarps_total);
    params_kernel<<<1, 128>>>(gamma, beta, lin_w, lin_b, n);
    final_kernel<<<(n * 32 + 255) / 256, 256>>>(out, n);
}

// round 15
// speedup vs baseline: 1.7079x; 1.0422x over previous
#include <cuda_runtime.h>
#include <cuda_fp16.h>
#include <mma.h>
#include <cstdint>

// Problem constants: N=50000, E=800000, IN_F=H_F=128, OUT_F=3
#define F 128
#define OUTF 3
#define BN_EPS 1e-5f
#define MAXN 50048
#define MAXE 800000
#define SCAN_TILE 4096
#define MAXTILES ((MAXN + SCAN_TILE - 1) / SCAN_TILE)

using namespace nvcuda;

// -------- device scratch (static; no dynamic allocations) --------
__device__ __align__(16) __half g_h[MAXN * F];   // x @ conv_w, fp16 storage
__device__ float  g_agg[MAXN * F];        // relu(agg + conv_b), fp32
__device__ float  g_dinv[MAXN];           // deg -> dinv (in place)
__device__ __align__(16) int g_cnt[MAXN]; // in-degree histogram
__device__ int    g_cur[MAXN];            // placement cursors
__device__ __align__(16) int g_off[MAXN + 16]; // CSR offsets (padded)
__device__ int    g_part[MAXTILES + 1];   // scan partials
__device__ __align__(16) int2 g_edge[MAXE]; // CSR: packed (src, norm-as-int)
__device__ float  g_sumf[F];              // BN sums
__device__ float  g_sumqf[F];             // BN sum of squares

// ---------------------------------------------------------------
// 1) init
__global__ void init_kernel(int n) {
    int i = blockIdx.x * blockDim.x + threadIdx.x;
    if (i < n) { g_dinv[i] = 1.0f; g_cnt[i] = 0; g_cur[i] = 0; }
    if (i < F) { g_sumf[i] = 0.0f; g_sumqf[i] = 0.0f; }
}

// 2) degree accumulation + in-degree histogram (edge_index is int32)
__global__ void deg_kernel(const int* __restrict__ ei,
                           const float* __restrict__ ew, int E) {
    int t = blockIdx.x * blockDim.x + threadIdx.x;
    int e = t * 2;
    if (e + 1 < E) {
        int2 c = *reinterpret_cast<const int2*>(ei + E + e);
        float2 w = *reinterpret_cast<const float2*>(ew + e);
        atomicAdd(&g_dinv[c.x], w.x);
        atomicAdd(&g_cnt[c.x], 1);
        atomicAdd(&g_dinv[c.y], w.y);
        atomicAdd(&g_cnt[c.y], 1);
    } else if (e < E) {
        int c = ei[E + e];
        atomicAdd(&g_dinv[c], ew[e]);
        atomicAdd(&g_cnt[c], 1);
    }
}

// 3) per-tile reduction (+ fused deg->dinv transform for the same range)
__global__ void scan_part_kernel(int n) {
    __shared__ int wsum[32];
    int b = blockIdx.x, tid = threadIdx.x;
    int base = b * SCAN_TILE + tid * 4;

#pragma unroll
    for (int k = 0; k < 4; k++) {
        int i = base + k;
        if (i < n) {
            float d = g_dinv[i];
            g_dinv[i] = (d > 0.0f) ? rsqrtf(d) : 0.0f;
        }
    }

    int4 v = make_int4(0, 0, 0, 0);
    if (base + 4 <= n) v = *reinterpret_cast<const int4*>(g_cnt + base);
    else {
        if (base + 0 < n) v.x = g_cnt[base + 0];
        if (base + 1 < n) v.y = g_cnt[base + 1];
        if (base + 2 < n) v.z = g_cnt[base + 2];
        if (base + 3 < n) v.w = g_cnt[base + 3];
    }
    int s = v.x + v.y + v.z + v.w;
    int lane = tid & 31, wid = tid >> 5;
#pragma unroll
    for (int off = 16; off > 0; off >>= 1) s += __shfl_down_sync(0xffffffffu, s, off);
    if (lane == 0) wsum[wid] = s;
    __syncthreads();
    if (wid == 0) {
        int t2 = wsum[lane];
#pragma unroll
        for (int off = 16; off > 0; off >>= 1) t2 += __shfl_down_sync(0xffffffffu, t2, off);
        if (lane == 0) g_part[b] = t2;
    }
}

// 4) per-tile exclusive scan-out with cross-tile prefix
__global__ void scan_out_kernel(int n, int ntiles) {
    __shared__ int wsum[32];
    int b = blockIdx.x, tid = threadIdx.x;
    int lane = tid & 31, wid = tid >> 5;

    int prefix = 0;
    for (int i = 0; i < b; i++) prefix += g_part[i];

    int base = b * SCAN_TILE + tid * 4;
    int4 v = make_int4(0, 0, 0, 0);
    bool full = (base + 4 <= n);
    if (full) v = *reinterpret_cast<const int4*>(g_cnt + base);
    else {
        if (base + 0 < n) v.x = g_cnt[base + 0];
        if (base + 1 < n) v.y = g_cnt[base + 1];
        if (base + 2 < n) v.z = g_cnt[base + 2];
        if (base + 3 < n) v.w = g_cnt[base + 3];
    }
    int s0 = v.x, s1 = s0 + v.y, s2 = s1 + v.z, s3 = s2 + v.w;

    int p = s3;
#pragma unroll
    for (int off = 1; off < 32; off <<= 1) {
        int tmp = __shfl_up_sync(0xffffffffu, p, off);
        if (lane >= off) p += tmp;
    }
    if (lane == 31) wsum[wid] = p;
    __syncthreads();
    if (wid == 0) {
        int w = wsum[lane];
#pragma unroll
        for (int off = 1; off < 32; off <<= 1) {
            int tmp = __shfl_up_sync(0xffffffffu, w, off);
            if (lane >= off) w += tmp;
        }
        wsum[lane] = w;
    }
    __syncthreads();

    int excl = prefix + (wid > 0 ? wsum[wid - 1] : 0) + (p - s3);
    if (full) {
        *reinterpret_cast<int4*>(g_off + base) =
            make_int4(excl, excl + s0, excl + s1, excl + s2);
    } else {
        if (base + 0 < n) g_off[base + 0] = excl;
        if (base + 1 < n) g_off[base + 1] = excl + s0;
        if (base + 2 < n) g_off[base + 2] = excl + s1;
        if (base + 3 < n) g_off[base + 3] = excl + s2;
    }
    if (b == ntiles - 1 && tid == 0) g_off[n] = prefix + g_part[b];
}

// 5) fill CSR slots: one packed int2 store per edge
__global__ void fill_kernel(const int* __restrict__ ei,
                            const float* __restrict__ ew, int E) {
    int e = blockIdx.x * blockDim.x + threadIdx.x;
    if (e >= E) return;
    int r = ei[e];
    int c = ei[E + e];
    int j = g_off[c] + atomicAdd(&g_cur[c], 1);
    float nrm = g_dinv[r] * ew[e] * g_dinv[c];
    g_edge[j] = make_int2(r, __float_as_int(nrm));
}

// ---------------------------------------------------------------
// 6) GEMM via HMMA: h[N,128] = x[N,128] @ w[128,128]
#define XLD 136   // half leading dim (padded)
__global__ __launch_bounds__(256)
void gemm_kernel(const float* __restrict__ x, const float* __restrict__ w, int n) {
    extern __shared__ __half sh[];
    __half* xs = sh;                 // [128][XLD]
    __half* ws = sh + 128 * XLD;     // [128][XLD]

    int tid = threadIdx.x;
    int lane = tid & 31;
    int warp = tid >> 5;             // 0..7
    int m0 = blockIdx.x * 128;

    for (int s = tid; s < 4096; s += 256) {
        int r = s >> 5, c4 = s & 31;
        float4 v = reinterpret_cast<const float4*>(w + (size_t)r * F)[c4];
        __half2 h0 = __floats2half2_rn(v.x, v.y);
        __half2 h1 = __floats2half2_rn(v.z, v.w);
        __half2* dst = reinterpret_cast<__half2*>(ws + r * XLD + c4 * 4);
        dst[0] = h0; dst[1] = h1;
    }
    for (int s = tid; s < 4096; s += 256) {
        int r = s >> 5, c4 = s & 31;
        float4 v = make_float4(0.f, 0.f, 0.f, 0.f);
        if (m0 + r < n)
            v = reinterpret_cast<const float4*>(x + (size_t)(m0 + r) * F)[c4];
        __half2 h0 = __floats2half2_rn(v.x, v.y);
        __half2 h1 = __floats2half2_rn(v.z, v.w);
        __half2* dst = reinterpret_cast<__half2*>(xs + r * XLD + c4 * 4);
        dst[0] = h0; dst[1] = h1;
    }
    __syncthreads();

    wmma::fragment<wmma::accumulator, 16, 16, 16, float> acc[8];
#pragma unroll
    for (int j = 0; j < 8; j++) wmma::fill_fragment(acc[j], 0.0f);

    int row0 = warp * 16;
#pragma unroll
    for (int k = 0; k < 128; k += 16) {
        wmma::fragment<wmma::matrix_a, 16, 16, 16, __half, wmma::row_major> a;
        wmma::load_matrix_sync(a, xs + row0 * XLD + k, XLD);
#pragma unroll
        for (int j = 0; j < 8; j++) {
            wmma::fragment<wmma::matrix_b, 16, 16, 16, __half, wmma::row_major> b;
            wmma::load_matrix_sync(b, ws + k * XLD + j * 16, XLD);
            wmma::mma_sync(acc[j], a, b, acc[j]);
        }
    }
    __syncthreads();

    float* cs = reinterpret_cast<float*>(sh);
    float* my = cs + warp * 16 * 128;
#pragma unroll
    for (int j = 0; j < 8; j++)
        wmma::store_matrix_sync(my + j * 16, acc[j], 128, wmma::mem_row_major);
    __syncwarp();

    for (int s = lane; s < 512; s += 32) {
        int r = s >> 5, c4 = s & 31;
        int node = m0 + row0 + r;
        if (node < n) {
            float4 v = reinterpret_cast<const float4*>(my + r * 128)[c4];
            __half2 h0 = __floats2half2_rn(v.x, v.y);
            __half2 h1 = __floats2half2_rn(v.z, v.w);
            uint2 u;
            u.x = *reinterpret_cast<unsigned*>(&h0);
            u.y = *reinterpret_cast<unsigned*>(&h1);
            reinterpret_cast<uint2*>(g_h + (size_t)node * F)[c4] = u;
        }
    }
}

// ---------------------------------------------------------------
// helper: load 4 features (fp16) of a row as floats
__device__ __forceinline__ void load_row4(int row, int lane,
                                          float& a, float& b, float& c, float& d) {
    uint2 u = reinterpret_cast<const uint2*>(g_h + (size_t)row * F)[lane];
    __half2 h0 = *reinterpret_cast<__half2*>(&u.x);
    __half2 h1 = *reinterpret_cast<__half2*>(&u.y);
    float2 f0 = __half22float2(h0);
    float2 f1 = __half22float2(h1);
    a = f0.x; b = f0.y; c = f1.x; d = f1.y;
}

// 7) fused gather + relu/bias + BN stats (persistent grid-stride)
__global__ __launch_bounds__(256)
void gather_kernel(const float* __restrict__ conv_b, int n, int nwarps_total) {
    __shared__ float sms[8][132];
    __shared__ float smq[8][132];

    int lane = threadIdx.x & 31;
    int w = threadIdx.x >> 5;
    int gwarp = blockIdx.x * 8 + w;

    int f = lane * 4;
    float b0 = __ldg(conv_b + f + 0), b1 = __ldg(conv_b + f + 1);
    float b2 = __ldg(conv_b + f + 2), b3 = __ldg(conv_b + f + 3);

    float s0 = 0.f, s1 = 0.f, s2 = 0.f, s3 = 0.f;   // BN sums
    float q0 = 0.f, q1 = 0.f, q2 = 0.f, q3 = 0.f;   // BN sumsq

    for (int node = gwarp; node < n; node += nwarps_total) {
        float d = g_dinv[node];
        float sc = d * d;
        float a0, a1, a2, a3;
        load_row4(node, lane, a0, a1, a2, a3);
        a0 *= sc; a1 *= sc; a2 *= sc; a3 *= sc;

        int j = g_off[node];
        int jend = g_off[node + 1];
        for (; j + 3 < jend; j += 4) {
            int2 e0 = g_edge[j],   e1 = g_edge[j+1];
            int2 e2 = g_edge[j+2], e3 = g_edge[j+3];
            float w0 = __int_as_float(e0.y), w1 = __int_as_float(e1.y);
            float w2 = __int_as_float(e2.y), w3 = __int_as_float(e3.y);
            float x0,x1,x2,x3, y0,y1,y2,y3, z0,z1,z2,z3, t0,t1,t2,t3;
            load_row4(e0.x, lane, x0, x1, x2, x3);
            load_row4(e1.x, lane, y0, y1, y2, y3);
            load_row4(e2.x, lane, z0, z1, z2, z3);
            load_row4(e3.x, lane, t0, t1, t2, t3);
            a0 += w0*x0 + w1*y0 + w2*z0 + w3*t0;
            a1 += w0*x1 + w1*y1 + w2*z1 + w3*t1;
            a2 += w0*x2 + w1*y2 + w2*z2 + w3*t2;
            a3 += w0*x3 + w1*y3 + w2*z3 + w3*t3;
        }
        for (; j < jend; j++) {
            int2 e = g_edge[j];
            float ww = __int_as_float(e.y);
            float x0, x1, x2, x3;
            load_row4(e.x, lane, x0, x1, x2, x3);
            a0 += ww*x0; a1 += ww*x1; a2 += ww*x2; a3 += ww*x3;
        }

        float r0 = fmaxf(a0 + b0, 0.f);
        float r1 = fmaxf(a1 + b1, 0.f);
        float r2 = fmaxf(a2 + b2, 0.f);
        float r3 = fmaxf(a3 + b3, 0.f);
        reinterpret_cast<float4*>(g_agg + (size_t)node * F)[lane] =
            make_float4(r0, r1, r2, r3);

        s0 += r0; s1 += r1; s2 += r2; s3 += r3;
        q0 += r0*r0; q1 += r1*r1; q2 += r2*r2; q3 += r3*r3;
    }

    sms[w][f + 0] = s0; sms[w][f + 1] = s1; sms[w][f + 2] = s2; sms[w][f + 3] = s3;
    smq[w][f + 0] = q0; smq[w][f + 1] = q1; smq[w][f + 2] = q2; smq[w][f + 3] = q3;
    __syncthreads();
    int t = threadIdx.x;
    if (t < F) {
        float s = 0.f, q = 0.f;
#pragma unroll
        for (int g = 0; g < 8; g++) { s += sms[g][t]; q += smq[g][t]; }
        atomicAdd(&g_sumf[t], s);
        atomicAdd(&g_sumqf[t], q);
    }
}

// 8) final (params folded in): each block derives w2/b2 from BN stats, then
//    grid-stride one-warp-per-node projection out[n,3] = r @ w2 + b2
__global__ __launch_bounds__(256)
void final_kernel(const float* __restrict__ gamma,
                  const float* __restrict__ beta,
                  const float* __restrict__ lin_w,
                  const float* __restrict__ lin_b,
                  float* __restrict__ out, int n, int nwarps_total) {
    __shared__ float w2s[F * OUTF];
    __shared__ float b2s[OUTF];
    __shared__ float partial[F][OUTF];

    int t = threadIdx.x;
    if (t < F) {
        float inv_n = 1.0f / (float)n;
        float mean = g_sumf[t] * inv_n;
        float var  = g_sumqf[t] * inv_n - mean * mean;
        float sc = gamma[t] * rsqrtf(var + BN_EPS);
        float sh = beta[t] - mean * sc;
#pragma unroll
        for (int o = 0; o < OUTF; o++) {
            float lw = lin_w[t * OUTF + o];
            w2s[t * OUTF + o] = sc * lw;
            partial[t][o] = sh * lw;
        }
    }
    __syncthreads();
    if (t < OUTF) {
        float s = lin_b[t];
        for (int i = 0; i < F; i++) s += partial[i][t];
        b2s[t] = s;
    }
    __syncthreads();

    int lane = t & 31;
    int w = t >> 5;
    for (int node = blockIdx.x * 8 + w; node < n; node += nwarps_total) {
        float4 v = reinterpret_cast<const float4*>(g_agg + (size_t)node * F)[lane];
        float r[4] = {v.x, v.y, v.z, v.w};

        float a0 = 0.f, a1 = 0.f, a2 = 0.f;
#pragma unroll
        for (int i = 0; i < 4; i++) {
            int f = lane * 4 + i;
            a0 += r[i] * w2s[f * OUTF + 0];
            a1 += r[i] * w2s[f * OUTF + 1];
            a2 += r[i] * w2s[f * OUTF + 2];
        }
#pragma unroll
        for (int off = 16; off > 0; off >>= 1) {
            a0 += __shfl_down_sync(0xffffffffu, a0, off);
            a1 += __shfl_down_sync(0xffffffffu, a1, off);
            a2 += __shfl_down_sync(0xffffffffu, a2, off);
        }
        if (lane == 0) {
            out[node * OUTF + 0] = a0 + b2s[0];
            out[node * OUTF + 1] = a1 + b2s[1];
            out[node * OUTF + 2] = a2 + b2s[2];
        }
    }
}

// ---------------------------------------------------------------
extern "C" void kernel_launch(void* const* d_in, const int* in_sizes, int n_in,
                              void* d_out, int out_size) {
    const float* x      = (const float*)d_in[0];
    const int*   ei     = (const int*)d_in[1];     // int32 (JAX x64 disabled)
    const float* ew     = (const float*)d_in[2];
    const float* conv_w = (const float*)d_in[3];
    const float* conv_b = (const float*)d_in[4];
    const float* gamma  = (const float*)d_in[5];
    const float* beta   = (const float*)d_in[6];
    const float* lin_w  = (const float*)d_in[7];
    const float* lin_b  = (const float*)d_in[8];
    float* out = (float*)d_out;

    int n = in_sizes[0] / F;        // 50000
    int E = in_sizes[2];            // 800000
    int ntiles = (n + SCAN_TILE - 1) / SCAN_TILE;

    const int GEMM_SMEM = 2 * 128 * XLD * (int)sizeof(__half);   // 69632 B
    static bool attr_set = false;
    if (!attr_set) {
        cudaFuncSetAttribute(gemm_kernel,
                             cudaFuncAttributeMaxDynamicSharedMemorySize, GEMM_SMEM);
        attr_set = true;
    }

    const int GATHER_BLOCKS = 1184;
    int nwarps_total = GATHER_BLOCKS * 8;

    init_kernel<<<(n + 255) / 256, 256>>>(n);
    deg_kernel<<<((E + 1) / 2 + 255) / 256, 256>>>(ei, ew, E);
    scan_part_kernel<<<ntiles, 1024>>>(n);
    scan_out_kernel<<<ntiles, 1024>>>(n, ntiles);
    fill_kernel<<<(E + 255) / 256, 256>>>(ei, ew, E);
    gemm_kernel<<<(n + 127) / 128, 256, GEMM_SMEM>>>(x, conv_w, n);
    gather_kernel<<<GATHER_BLOCKS, 256>>>(conv_b, n, nwarps_total);
    final_kernel<<<GATHER_BLOCKS, 256>>>(gamma, beta, lin_w, lin_b, out, n, nwarps_total);
}